// round 1
// baseline (speedup 1.0000x reference)
#include <cuda_runtime.h>
#include <math.h>

#define N_CFG 400000
#define E_CFG 1600000
#define N_FUNC 8000
#define N_FCG 9600
#define E_FCG 80000
#define NB 8
#define D_H 128
#define VOCAB 10002

// ---------------- scratch (device globals; no allocation allowed) ----------
__device__ float g_hs[(size_t)N_CFG * D_H];   // h * dis[row] (per layer)
__device__ float g_x [(size_t)N_CFG * D_H];   // layer output accumulator
__device__ float g_dis[N_CFG];
__device__ float g_fdis[N_FCG];
__device__ float g_pool[N_FUNC * D_H];
__device__ float g_cnt[N_FUNC];
__device__ float g_fx [N_FCG * D_H];
__device__ float g_fhs[N_FCG * D_H];
__device__ float g_fy [N_FCG * D_H];
__device__ float g_g  [NB * D_H];
__device__ float g_gc [NB];

// ---------------- utility kernels ------------------------------------------
#define ZLIM (N_FUNC * D_H)   // 1,024,000 : the largest zeroed extent
__global__ void zero_kernel() {
    int i = blockIdx.x * blockDim.x + threadIdx.x;
    int stride = gridDim.x * blockDim.x;
    for (; i < ZLIM; i += stride) {
        if (i < N_CFG)        g_dis[i]  = 0.f;
        if (i < N_FCG)        g_fdis[i] = 0.f;
        if (i < N_FUNC * D_H) g_pool[i] = 0.f;
        if (i < N_FUNC)       g_cnt[i]  = 0.f;
        if (i < NB * D_H)     g_g[i]    = 0.f;
        if (i < NB)           g_gc[i]   = 0.f;
    }
}

__global__ void deg_kernel(const int* __restrict__ ei, int E, float* __restrict__ deg) {
    int i = blockIdx.x * blockDim.x + threadIdx.x;
    if (i < E) atomicAdd(&deg[ei[E + i]], 1.0f);   // destination = col (second row)
}

__global__ void rsqrt_kernel(float* __restrict__ d, int n) {
    int i = blockIdx.x * blockDim.x + threadIdx.x;
    if (i < n) d[i] = rsqrtf(d[i] + 1.0f);
}

// ---------------- GEMM: H[row] = (relu?)(X[row]) @ W  * dis[row] ------------
// Block tile: 64 rows x 128 cols, 256 threads, each thread 4x8 register tile.
template<int K, bool RELU>
__global__ __launch_bounds__(256) void gemm_kernel(
    const float* __restrict__ X, const float* __restrict__ W,
    const float* __restrict__ dis, float* __restrict__ H, int N) {
    __shared__ float Ws[64 * 128];   // 32 KB (one 64-row K-chunk of W)
    __shared__ float Xs[64 * 64];    // 16 KB
    const int row0 = blockIdx.x * 64;
    const int tx = threadIdx.x & 15;   // col group: cols tx + c*16
    const int ty = threadIdx.x >> 4;   // row group: rows ty*4 + r
    float acc[4][8];
#pragma unroll
    for (int r = 0; r < 4; r++)
#pragma unroll
        for (int c = 0; c < 8; c++) acc[r][c] = 0.f;

    for (int kc = 0; kc < K; kc += 64) {
        for (int i = threadIdx.x; i < 64 * 128; i += 256) Ws[i] = W[kc * 128 + i];
        for (int i = threadIdx.x; i < 64 * 64; i += 256) {
            int r = i >> 6, k = i & 63;
            int gr = row0 + r;
            float v = (gr < N) ? X[(size_t)gr * K + kc + k] : 0.f;
            Xs[i] = RELU ? fmaxf(v, 0.f) : v;
        }
        __syncthreads();
#pragma unroll 4
        for (int k = 0; k < 64; k++) {
            float w[8], a[4];
#pragma unroll
            for (int c = 0; c < 8; c++) w[c] = Ws[k * 128 + tx + c * 16];
#pragma unroll
            for (int r = 0; r < 4; r++) a[r] = Xs[(ty * 4 + r) * 64 + k];
#pragma unroll
            for (int r = 0; r < 4; r++)
#pragma unroll
                for (int c = 0; c < 8; c++) acc[r][c] += a[r] * w[c];
        }
        __syncthreads();
    }
#pragma unroll
    for (int r = 0; r < 4; r++) {
        int gr = row0 + ty * 4 + r;
        if (gr < N) {
            float s = dis[gr];
#pragma unroll
            for (int c = 0; c < 8; c++)
                H[(size_t)gr * 128 + tx + c * 16] = acc[r][c] * s;
        }
    }
}

// x[i,j] = hs[i,j]*dis[i] + b[j]   (self-loop term + bias; hs already has one dis)
__global__ void selfinit_kernel(const float4* __restrict__ hs, const float* __restrict__ dis,
                                const float4* __restrict__ b, float4* __restrict__ x, int n) {
    int i = blockIdx.x * blockDim.x + threadIdx.x;   // over n*32 float4s
    if (i >= n * 32) return;
    int row = i >> 5, jq = i & 31;
    float s = dis[row];
    float4 h = hs[i], bb = b[jq];
    float4 o;
    o.x = h.x * s + bb.x; o.y = h.y * s + bb.y;
    o.z = h.z * s + bb.z; o.w = h.w * s + bb.w;
    x[i] = o;
}

// one warp per edge: x[col] += hs[row] * dis[col]
__global__ __launch_bounds__(256) void scatter_kernel(
    const int* __restrict__ ei, int E,
    const float* __restrict__ hs, const float* __restrict__ dis,
    float* __restrict__ x) {
    int warp = (blockIdx.x * 256 + threadIdx.x) >> 5;
    int lane = threadIdx.x & 31;
    if (warp >= E) return;
    int r = ei[warp], c = ei[E + warp];
    float nc = dis[c];
    float4 v = ((const float4*)(hs + (size_t)r * 128))[lane];
    float* dst = x + (size_t)c * 128 + lane * 4;
    atomicAdd(dst + 0, v.x * nc);
    atomicAdd(dst + 1, v.y * nc);
    atomicAdd(dst + 2, v.z * nc);
    atomicAdd(dst + 3, v.w * nc);
}

// one warp per node: pool[seg] += relu(x[node]); cnt[seg] += 1
__global__ __launch_bounds__(256) void pool_kernel(
    const float* __restrict__ x, const int* __restrict__ seg,
    float* __restrict__ pool, float* __restrict__ cnt, int n) {
    int warp = (blockIdx.x * 256 + threadIdx.x) >> 5;
    int lane = threadIdx.x & 31;
    if (warp >= n) return;
    int f = seg[warp];
    float4 v = ((const float4*)(x + (size_t)warp * 128))[lane];
    v.x = fmaxf(v.x, 0.f); v.y = fmaxf(v.y, 0.f);
    v.z = fmaxf(v.z, 0.f); v.w = fmaxf(v.w, 0.f);
    float* dst = pool + (size_t)f * 128 + lane * 4;
    atomicAdd(dst + 0, v.x);
    atomicAdd(dst + 1, v.y);
    atomicAdd(dst + 2, v.z);
    atomicAdd(dst + 3, v.w);
    if (lane == 0) atomicAdd(&cnt[f], 1.0f);
}

__global__ void pooldiv_kernel(float* __restrict__ pool, const float* __restrict__ cnt, int nseg) {
    int i = blockIdx.x * blockDim.x + threadIdx.x;
    if (i < nseg * D_H) pool[i] = pool[i] / fmaxf(cnt[i >> 7], 1.0f);
}

__global__ void assemble_kernel(const float* __restrict__ pool, const float* __restrict__ emb,
                                const int* __restrict__ src, const int* __restrict__ isext,
                                float* __restrict__ fx) {
    int i = blockIdx.x * blockDim.x + threadIdx.x;
    if (i >= N_FCG * D_H) return;
    int row = i >> 7, j = i & 127;
    int s = src[row];
    float v;
    if (isext[row] == 1) {
        int k = min(max(s, 0), VOCAB - 1);
        v = emb[(size_t)k * D_H + j];
    } else {
        int k = min(max(s, 0), N_FUNC - 1);
        v = pool[(size_t)k * D_H + j];
    }
    fx[i] = v;
}

// final mean-div + MLP head + sigmoid (tiny; single block)
__global__ __launch_bounds__(256) void head_kernel(
    const float* __restrict__ gsum, const float* __restrict__ gcnt,
    const float* __restrict__ Wp1, const float* __restrict__ bp1,
    const float* __restrict__ Wp2, const float* __restrict__ bp2,
    const float* __restrict__ Wp3, const float* __restrict__ bp3,
    float* __restrict__ out) {
    __shared__ float G[NB * 128], H1[NB * 64], H2[NB * 32];
    int t = threadIdx.x;
    for (int i = t; i < NB * 128; i += 256) G[i] = gsum[i] / fmaxf(gcnt[i >> 7], 1.0f);
    __syncthreads();
    for (int i = t; i < NB * 64; i += 256) {
        int r = i >> 6, c = i & 63;
        float a = bp1[c];
        for (int k = 0; k < 128; k++) a += G[r * 128 + k] * Wp1[k * 64 + c];
        H1[i] = fmaxf(a, 0.f);
    }
    __syncthreads();
    for (int i = t; i < NB * 32; i += 256) {
        int r = i >> 5, c = i & 31;
        float a = bp2[c];
        for (int k = 0; k < 64; k++) a += H1[r * 64 + k] * Wp2[k * 32 + c];
        H2[i] = fmaxf(a, 0.f);
    }
    __syncthreads();
    if (t < NB) {
        float a = bp3[0];
        for (int k = 0; k < 32; k++) a += H2[t * 32 + k] * Wp3[k];
        out[t] = 1.0f / (1.0f + expf(-a));
    }
}

// ---------------- launch ----------------------------------------------------
extern "C" void kernel_launch(void* const* d_in, const int* in_sizes, int n_in,
                              void* d_out, int out_size) {
    const float* cfg_x  = (const float*)d_in[0];
    const int*   cfg_ei = (const int*)  d_in[1];
    const int*   n2f    = (const int*)  d_in[2];
    const int*   fcg_ei = (const int*)  d_in[3];
    const int*   fbatch = (const int*)  d_in[4];
    const int*   fsrc   = (const int*)  d_in[5];
    const int*   fext   = (const int*)  d_in[6];
    const float* W1  = (const float*)d_in[7];
    const float* b1  = (const float*)d_in[8];
    const float* W2  = (const float*)d_in[9];
    const float* b2  = (const float*)d_in[10];
    const float* emb = (const float*)d_in[11];
    const float* Wf  = (const float*)d_in[12];
    const float* bf  = (const float*)d_in[13];
    const float* Wp1 = (const float*)d_in[14];
    const float* bp1 = (const float*)d_in[15];
    const float* Wp2 = (const float*)d_in[16];
    const float* bp2 = (const float*)d_in[17];
    const float* Wp3 = (const float*)d_in[18];
    const float* bp3 = (const float*)d_in[19];
    float* out = (float*)d_out;

    void *p;
    cudaGetSymbolAddress(&p, g_hs);   float* hs   = (float*)p;
    cudaGetSymbolAddress(&p, g_x);    float* x    = (float*)p;
    cudaGetSymbolAddress(&p, g_dis);  float* dis  = (float*)p;
    cudaGetSymbolAddress(&p, g_fdis); float* fdis = (float*)p;
    cudaGetSymbolAddress(&p, g_pool); float* pool = (float*)p;
    cudaGetSymbolAddress(&p, g_cnt);  float* cnt  = (float*)p;
    cudaGetSymbolAddress(&p, g_fx);   float* fx   = (float*)p;
    cudaGetSymbolAddress(&p, g_fhs);  float* fhs  = (float*)p;
    cudaGetSymbolAddress(&p, g_fy);   float* fy   = (float*)p;
    cudaGetSymbolAddress(&p, g_g);    float* gg   = (float*)p;
    cudaGetSymbolAddress(&p, g_gc);   float* gc   = (float*)p;

    // zero scratch + degrees
    zero_kernel<<<4000, 256>>>();
    deg_kernel<<<(E_CFG + 255) / 256, 256>>>(cfg_ei, E_CFG, dis);
    deg_kernel<<<(E_FCG + 255) / 256, 256>>>(fcg_ei, E_FCG, fdis);
    rsqrt_kernel<<<(N_CFG + 255) / 256, 256>>>(dis, N_CFG);
    rsqrt_kernel<<<(N_FCG + 255) / 256, 256>>>(fdis, N_FCG);

    // CFG GCN layer 1
    gemm_kernel<64, false><<<N_CFG / 64, 256>>>(cfg_x, W1, dis, hs, N_CFG);
    selfinit_kernel<<<(N_CFG * 32) / 256, 256>>>((const float4*)hs, dis, (const float4*)b1, (float4*)x, N_CFG);
    scatter_kernel<<<E_CFG / 8, 256>>>(cfg_ei, E_CFG, hs, dis, x);

    // CFG GCN layer 2 (relu of layer-1 output fused into GEMM load)
    gemm_kernel<128, true><<<N_CFG / 64, 256>>>(x, W2, dis, hs, N_CFG);
    selfinit_kernel<<<(N_CFG * 32) / 256, 256>>>((const float4*)hs, dis, (const float4*)b2, (float4*)x, N_CFG);
    scatter_kernel<<<E_CFG / 8, 256>>>(cfg_ei, E_CFG, hs, dis, x);

    // function-level mean pool (relu fused into pool read)
    pool_kernel<<<N_CFG / 8, 256>>>(x, n2f, pool, cnt, N_CFG);
    pooldiv_kernel<<<(N_FUNC * D_H) / 256, 256>>>(pool, cnt, N_FUNC);

    // FCG features + FCG GCN layer
    assemble_kernel<<<(N_FCG * D_H) / 256, 256>>>(pool, emb, fsrc, fext, fx);
    gemm_kernel<128, false><<<N_FCG / 64, 256>>>(fx, Wf, fdis, fhs, N_FCG);
    selfinit_kernel<<<(N_FCG * 32) / 256, 256>>>((const float4*)fhs, fdis, (const float4*)bf, (float4*)fy, N_FCG);
    scatter_kernel<<<E_FCG / 8, 256>>>(fcg_ei, E_FCG, fhs, fdis, fy);

    // binary-level mean pool (relu fused) + head
    pool_kernel<<<N_FCG / 8, 256>>>(fy, fbatch, gg, gc, N_FCG);
    head_kernel<<<1, 256>>>(gg, gc, Wp1, bp1, Wp2, bp2, Wp3, bp3, out);
}

// round 2
// speedup vs baseline: 1.8631x; 1.8631x over previous
#include <cuda_runtime.h>
#include <math.h>

#define N_CFG 400000
#define E_CFG 1600000
#define N_FUNC 8000
#define N_FCG 9600
#define E_FCG 80000
#define NB 8
#define D_H 128
#define VOCAB 10002

// ---------------- scratch (device globals) ----------------------------------
__device__ float g_hs[(size_t)N_CFG * D_H];
__device__ float g_x [(size_t)N_CFG * D_H];
__device__ int   g_deg[N_CFG];
__device__ float g_dis[N_CFG];
__device__ int   g_rowptr[N_CFG];
__device__ int   g_cursor[N_CFG];
__device__ int   g_csr[E_CFG];
__device__ int   g_fdeg[N_FCG];
__device__ float g_fdis[N_FCG];
__device__ int   g_frowptr[N_FCG];
__device__ int   g_fcursor[N_FCG];
__device__ int   g_fcsr[E_FCG];
__device__ int   g_bsum[512];
__device__ int   g_fstart[N_FUNC + 1];
__device__ int   g_bstart[NB + 1];
__device__ float g_pool[N_FUNC * D_H];
__device__ float g_fx [N_FCG * D_H];
__device__ float g_fhs[N_FCG * D_H];
__device__ float g_fy [N_FCG * D_H];
__device__ float g_g  [NB * D_H];

// ---------------- degree / norm ---------------------------------------------
__global__ void zerodeg_kernel() {
    int i = blockIdx.x * blockDim.x + threadIdx.x;
    if (i < N_CFG) g_deg[i] = 0;
    if (i < N_FCG) g_fdeg[i] = 0;
}
__global__ void degi_kernel(const int* __restrict__ ei, int E, int* __restrict__ deg) {
    int i = blockIdx.x * blockDim.x + threadIdx.x;
    if (i < E) atomicAdd(&deg[ei[E + i]], 1);
}
__global__ void dis_kernel(const int* __restrict__ deg, float* __restrict__ dis, int n) {
    int i = blockIdx.x * blockDim.x + threadIdx.x;
    if (i < n) dis[i] = rsqrtf((float)deg[i] + 1.0f);
}

// ---------------- CSR build: scan + fill ------------------------------------
__global__ void scan_local(const int* __restrict__ cnt, int n, int* __restrict__ out,
                           int* __restrict__ bsum) {
    __shared__ int s[256];
    int base = blockIdx.x * 1024;
    int t = threadIdx.x;
    int v[4], sum = 0;
#pragma unroll
    for (int j = 0; j < 4; j++) {
        int i = base + t * 4 + j;
        v[j] = (i < n) ? cnt[i] : 0;
        sum += v[j];
    }
    s[t] = sum;
    __syncthreads();
    for (int off = 1; off < 256; off <<= 1) {
        int x = (t >= off) ? s[t - off] : 0;
        __syncthreads();
        s[t] += x;
        __syncthreads();
    }
    if (t == 255) bsum[blockIdx.x] = s[255];
    int run = (t > 0) ? s[t - 1] : 0;
#pragma unroll
    for (int j = 0; j < 4; j++) {
        int i = base + t * 4 + j;
        if (i < n) out[i] = run;
        run += v[j];
    }
}
__global__ void scan_bsum(int* __restrict__ bsum, int nb) {
    __shared__ int s[512];
    int t = threadIdx.x;
    s[t] = (t < nb) ? bsum[t] : 0;
    __syncthreads();
    for (int off = 1; off < 512; off <<= 1) {
        int x = (t >= off) ? s[t - off] : 0;
        __syncthreads();
        s[t] += x;
        __syncthreads();
    }
    if (t < nb) bsum[t] = (t > 0) ? s[t - 1] : 0;
}
__global__ void scan_add(int* __restrict__ out, const int* __restrict__ bsum, int n,
                         int* __restrict__ cursor) {
    int i = blockIdx.x * blockDim.x + threadIdx.x;
    if (i < n) {
        int v = out[i] + bsum[i >> 10];
        out[i] = v;
        cursor[i] = v;
    }
}
__global__ void fill_csr(const int* __restrict__ ei, int E, int* __restrict__ cursor,
                         int* __restrict__ csr) {
    int i = blockIdx.x * blockDim.x + threadIdx.x;
    if (i < E) {
        int r = ei[i], c = ei[E + i];
        int slot = atomicAdd(&cursor[c], 1);
        csr[slot] = r;
    }
}

// segment start via binary search over a sorted seg array (start[nseg] = n)
__global__ void seg_bounds(const int* __restrict__ seg, int n, int nseg, int* __restrict__ start) {
    int f = blockIdx.x * blockDim.x + threadIdx.x;
    if (f > nseg) return;
    int lo = 0, hi = n;
    while (lo < hi) {
        int mid = (lo + hi) >> 1;
        if (seg[mid] < f) lo = mid + 1; else hi = mid;
    }
    start[f] = lo;
}

// ---------------- GEMM: H[row] = (relu?)(X[row]) @ W  * dis[row] ------------
template<int K, bool RELU>
__global__ __launch_bounds__(256) void gemm_kernel(
    const float* __restrict__ X, const float* __restrict__ W,
    const float* __restrict__ dis, float* __restrict__ H, int N) {
    __shared__ float Ws[64 * 128];
    __shared__ float Xs[64 * 64];
    const int row0 = blockIdx.x * 64;
    const int tx = threadIdx.x & 15;
    const int ty = threadIdx.x >> 4;
    float acc[4][8];
#pragma unroll
    for (int r = 0; r < 4; r++)
#pragma unroll
        for (int c = 0; c < 8; c++) acc[r][c] = 0.f;

    for (int kc = 0; kc < K; kc += 64) {
        for (int i = threadIdx.x; i < 64 * 128; i += 256) Ws[i] = W[kc * 128 + i];
        for (int i = threadIdx.x; i < 64 * 64; i += 256) {
            int r = i >> 6, k = i & 63;
            int gr = row0 + r;
            float v = (gr < N) ? X[(size_t)gr * K + kc + k] : 0.f;
            Xs[i] = RELU ? fmaxf(v, 0.f) : v;
        }
        __syncthreads();
#pragma unroll 4
        for (int k = 0; k < 64; k++) {
            float w[8], a[4];
#pragma unroll
            for (int c = 0; c < 8; c++) w[c] = Ws[k * 128 + tx + c * 16];
#pragma unroll
            for (int r = 0; r < 4; r++) a[r] = Xs[(ty * 4 + r) * 64 + k];
#pragma unroll
            for (int r = 0; r < 4; r++)
#pragma unroll
                for (int c = 0; c < 8; c++) acc[r][c] += a[r] * w[c];
        }
        __syncthreads();
    }
#pragma unroll
    for (int r = 0; r < 4; r++) {
        int gr = row0 + ty * 4 + r;
        if (gr < N) {
            float s = dis[gr];
#pragma unroll
            for (int c = 0; c < 8; c++)
                H[(size_t)gr * 128 + tx + c * 16] = acc[r][c] * s;
        }
    }
}

// ---------------- gather: out[v] = (hs[v] + sum_{u->v} hs[u]) * dis[v] + b ---
__global__ __launch_bounds__(256) void gather_kernel(
    const int* __restrict__ rowptr, const int* __restrict__ deg,
    const int* __restrict__ csr, const float* __restrict__ hs,
    const float* __restrict__ dis, const float4* __restrict__ b,
    float4* __restrict__ out, int n) {
    int node = (blockIdx.x * 256 + threadIdx.x) >> 5;
    int lane = threadIdx.x & 31;
    if (node >= n) return;
    const float4* hs4 = (const float4*)hs;
    float4 acc = hs4[(size_t)node * 32 + lane];   // self-loop (already × dis[node] once)
    int start = rowptr[node], d = deg[node];
    for (int e = 0; e < d; e++) {
        int s = csr[start + e];
        float4 v = hs4[(size_t)s * 32 + lane];
        acc.x += v.x; acc.y += v.y; acc.z += v.z; acc.w += v.w;
    }
    float dc = dis[node];
    float4 bb = b[lane];
    float4 o;
    o.x = acc.x * dc + bb.x; o.y = acc.y * dc + bb.y;
    o.z = acc.z * dc + bb.z; o.w = acc.w * dc + bb.w;
    out[(size_t)node * 32 + lane] = o;
}

// ---------------- function-level mean pool (sorted segments, relu fused) -----
__global__ __launch_bounds__(256) void poolseg_kernel(
    const float* __restrict__ x, const int* __restrict__ start,
    float* __restrict__ pool, int nseg) {
    int f = (blockIdx.x * 256 + threadIdx.x) >> 5;
    int lane = threadIdx.x & 31;
    if (f >= nseg) return;
    int s = start[f], e = start[f + 1];
    const float4* x4 = (const float4*)x;
    float4 acc = make_float4(0.f, 0.f, 0.f, 0.f);
    for (int i = s; i < e; i++) {
        float4 v = x4[(size_t)i * 32 + lane];
        acc.x += fmaxf(v.x, 0.f); acc.y += fmaxf(v.y, 0.f);
        acc.z += fmaxf(v.z, 0.f); acc.w += fmaxf(v.w, 0.f);
    }
    float inv = 1.0f / (float)max(e - s, 1);
    acc.x *= inv; acc.y *= inv; acc.z *= inv; acc.w *= inv;
    ((float4*)pool)[(size_t)f * 32 + lane] = acc;
}

__global__ void assemble_kernel(const float* __restrict__ pool, const float* __restrict__ emb,
                                const int* __restrict__ src, const int* __restrict__ isext,
                                float* __restrict__ fx) {
    int i = blockIdx.x * blockDim.x + threadIdx.x;
    if (i >= N_FCG * D_H) return;
    int row = i >> 7, j = i & 127;
    int s = src[row];
    float v;
    if (isext[row] == 1) {
        int k = min(max(s, 0), VOCAB - 1);
        v = emb[(size_t)k * D_H + j];
    } else {
        int k = min(max(s, 0), N_FUNC - 1);
        v = pool[(size_t)k * D_H + j];
    }
    fx[i] = v;
}

// binary-level mean pool: block per binary, thread per channel (relu fused)
__global__ __launch_bounds__(128) void gpool_kernel(
    const float* __restrict__ y, const int* __restrict__ start, float* __restrict__ g) {
    int b = blockIdx.x, col = threadIdx.x;
    int s = start[b], e = start[b + 1];
    float acc = 0.f;
    for (int i = s; i < e; i++) acc += fmaxf(y[(size_t)i * 128 + col], 0.f);
    g[b * 128 + col] = acc / (float)max(e - s, 1);
}

// MLP head + sigmoid (tiny; single block)
__global__ __launch_bounds__(256) void head_kernel(
    const float* __restrict__ g,
    const float* __restrict__ Wp1, const float* __restrict__ bp1,
    const float* __restrict__ Wp2, const float* __restrict__ bp2,
    const float* __restrict__ Wp3, const float* __restrict__ bp3,
    float* __restrict__ out) {
    __shared__ float G[NB * 128], H1[NB * 64], H2[NB * 32];
    int t = threadIdx.x;
    for (int i = t; i < NB * 128; i += 256) G[i] = g[i];
    __syncthreads();
    for (int i = t; i < NB * 64; i += 256) {
        int r = i >> 6, c = i & 63;
        float a = bp1[c];
        for (int k = 0; k < 128; k++) a += G[r * 128 + k] * Wp1[k * 64 + c];
        H1[i] = fmaxf(a, 0.f);
    }
    __syncthreads();
    for (int i = t; i < NB * 32; i += 256) {
        int r = i >> 5, c = i & 31;
        float a = bp2[c];
        for (int k = 0; k < 64; k++) a += H1[r * 64 + k] * Wp2[k * 32 + c];
        H2[i] = fmaxf(a, 0.f);
    }
    __syncthreads();
    if (t < NB) {
        float a = bp3[0];
        for (int k = 0; k < 32; k++) a += H2[t * 32 + k] * Wp3[k];
        out[t] = 1.0f / (1.0f + expf(-a));
    }
}

// ---------------- launch ----------------------------------------------------
extern "C" void kernel_launch(void* const* d_in, const int* in_sizes, int n_in,
                              void* d_out, int out_size) {
    const float* cfg_x  = (const float*)d_in[0];
    const int*   cfg_ei = (const int*)  d_in[1];
    const int*   n2f    = (const int*)  d_in[2];
    const int*   fcg_ei = (const int*)  d_in[3];
    const int*   fbatch = (const int*)  d_in[4];
    const int*   fsrc   = (const int*)  d_in[5];
    const int*   fext   = (const int*)  d_in[6];
    const float* W1  = (const float*)d_in[7];
    const float* b1  = (const float*)d_in[8];
    const float* W2  = (const float*)d_in[9];
    const float* b2  = (const float*)d_in[10];
    const float* emb = (const float*)d_in[11];
    const float* Wf  = (const float*)d_in[12];
    const float* bf  = (const float*)d_in[13];
    const float* Wp1 = (const float*)d_in[14];
    const float* bp1 = (const float*)d_in[15];
    const float* Wp2 = (const float*)d_in[16];
    const float* bp2 = (const float*)d_in[17];
    const float* Wp3 = (const float*)d_in[18];
    const float* bp3 = (const float*)d_in[19];
    float* out = (float*)d_out;

    void *p;
    cudaGetSymbolAddress(&p, g_hs);      float* hs     = (float*)p;
    cudaGetSymbolAddress(&p, g_x);       float* x      = (float*)p;
    cudaGetSymbolAddress(&p, g_deg);     int*   deg    = (int*)p;
    cudaGetSymbolAddress(&p, g_dis);     float* dis    = (float*)p;
    cudaGetSymbolAddress(&p, g_rowptr);  int*   rowptr = (int*)p;
    cudaGetSymbolAddress(&p, g_cursor);  int*   cursor = (int*)p;
    cudaGetSymbolAddress(&p, g_csr);     int*   csr    = (int*)p;
    cudaGetSymbolAddress(&p, g_fdeg);    int*   fdeg   = (int*)p;
    cudaGetSymbolAddress(&p, g_fdis);    float* fdis   = (float*)p;
    cudaGetSymbolAddress(&p, g_frowptr); int*   frowptr= (int*)p;
    cudaGetSymbolAddress(&p, g_fcursor); int*   fcursor= (int*)p;
    cudaGetSymbolAddress(&p, g_fcsr);    int*   fcsr   = (int*)p;
    cudaGetSymbolAddress(&p, g_bsum);    int*   bsum   = (int*)p;
    cudaGetSymbolAddress(&p, g_fstart);  int*   fstart = (int*)p;
    cudaGetSymbolAddress(&p, g_bstart);  int*   bstart = (int*)p;
    cudaGetSymbolAddress(&p, g_pool);    float* pool   = (float*)p;
    cudaGetSymbolAddress(&p, g_fx);      float* fx     = (float*)p;
    cudaGetSymbolAddress(&p, g_fhs);     float* fhs    = (float*)p;
    cudaGetSymbolAddress(&p, g_fy);      float* fy     = (float*)p;
    cudaGetSymbolAddress(&p, g_g);       float* gg     = (float*)p;

    // degrees + norms
    zerodeg_kernel<<<(N_CFG + 255) / 256, 256>>>();
    degi_kernel<<<(E_CFG + 255) / 256, 256>>>(cfg_ei, E_CFG, deg);
    degi_kernel<<<(E_FCG + 255) / 256, 256>>>(fcg_ei, E_FCG, fdeg);
    dis_kernel<<<(N_CFG + 255) / 256, 256>>>(deg, dis, N_CFG);
    dis_kernel<<<(N_FCG + 255) / 256, 256>>>(fdeg, fdis, N_FCG);

    // CSR build (CFG)
    const int NBLK_CFG = (N_CFG + 1023) / 1024;   // 391
    scan_local<<<NBLK_CFG, 256>>>(deg, N_CFG, rowptr, bsum);
    scan_bsum<<<1, 512>>>(bsum, NBLK_CFG);
    scan_add<<<(N_CFG + 255) / 256, 256>>>(rowptr, bsum, N_CFG, cursor);
    fill_csr<<<(E_CFG + 255) / 256, 256>>>(cfg_ei, E_CFG, cursor, csr);

    // CSR build (FCG)
    const int NBLK_FCG = (N_FCG + 1023) / 1024;   // 10
    scan_local<<<NBLK_FCG, 256>>>(fdeg, N_FCG, frowptr, bsum);
    scan_bsum<<<1, 512>>>(bsum, NBLK_FCG);
    scan_add<<<(N_FCG + 255) / 256, 256>>>(frowptr, bsum, N_FCG, fcursor);
    fill_csr<<<(E_FCG + 255) / 256, 256>>>(fcg_ei, E_FCG, fcursor, fcsr);

    // sorted-segment bounds
    seg_bounds<<<(N_FUNC + 256) / 256, 256>>>(n2f, N_CFG, N_FUNC, fstart);
    seg_bounds<<<1, 32>>>(fbatch, N_FCG, NB, bstart);

    // CFG GCN layer 1
    gemm_kernel<64, false><<<N_CFG / 64, 256>>>(cfg_x, W1, dis, hs, N_CFG);
    gather_kernel<<<(N_CFG * 32 + 255) / 256, 256>>>(rowptr, deg, csr, hs, dis,
                                                     (const float4*)b1, (float4*)x, N_CFG);
    // CFG GCN layer 2 (relu fused into GEMM load)
    gemm_kernel<128, true><<<N_CFG / 64, 256>>>(x, W2, dis, hs, N_CFG);
    gather_kernel<<<(N_CFG * 32 + 255) / 256, 256>>>(rowptr, deg, csr, hs, dis,
                                                     (const float4*)b2, (float4*)x, N_CFG);

    // function-level mean pool (relu fused)
    poolseg_kernel<<<(N_FUNC * 32 + 255) / 256, 256>>>(x, fstart, pool, N_FUNC);

    // FCG features + FCG GCN layer
    assemble_kernel<<<(N_FCG * D_H) / 256, 256>>>(pool, emb, fsrc, fext, fx);
    gemm_kernel<128, false><<<N_FCG / 64, 256>>>(fx, Wf, fdis, fhs, N_FCG);
    gather_kernel<<<(N_FCG * 32 + 255) / 256, 256>>>(frowptr, fdeg, fcsr, fhs, fdis,
                                                     (const float4*)bf, (float4*)fy, N_FCG);

    // binary-level mean pool (relu fused) + head
    gpool_kernel<<<NB, 128>>>(fy, bstart, gg);
    head_kernel<<<1, 256>>>(gg, Wp1, bp1, Wp2, bp2, Wp3, bp3, out);
}

// round 3
// speedup vs baseline: 2.2511x; 1.2082x over previous
#include <cuda_runtime.h>
#include <math.h>

#define N_CFG 400000
#define E_CFG 1600000
#define N_FUNC 8000
#define N_FCG 9600
#define E_FCG 80000
#define NB 8
#define D_H 128
#define VOCAB 10002

// ---------------- scratch (device globals) ----------------------------------
__device__ float g_a [(size_t)N_CFG * D_H];   // ping
__device__ float g_b [(size_t)N_CFG * D_H];   // pong
__device__ int   g_deg[N_CFG];
__device__ float g_dis[N_CFG];
__device__ int   g_rowptr[N_CFG];
__device__ int   g_cursor[N_CFG];
__device__ int   g_csr[E_CFG];
__device__ int   g_fdeg[N_FCG];
__device__ float g_fdis[N_FCG];
__device__ int   g_frowptr[N_FCG];
__device__ int   g_fcursor[N_FCG];
__device__ int   g_fcsr[E_FCG];
__device__ int   g_bsum[512];
__device__ int   g_fstart[N_FUNC + 1];
__device__ int   g_bstart[NB + 1];
__device__ float g_pool[N_FUNC * D_H];
__device__ float g_fx [N_FCG * D_H];
__device__ float g_fz [N_FCG * D_H];
__device__ float g_fy [N_FCG * D_H];
__device__ float g_g  [NB * D_H];

// ---------------- degree / norm ---------------------------------------------
__global__ void zerodeg_kernel() {
    int i = blockIdx.x * blockDim.x + threadIdx.x;
    if (i < N_CFG) g_deg[i] = 0;
    if (i < N_FCG) g_fdeg[i] = 0;
}
__global__ void degi_kernel(const int* __restrict__ ei, int E, int* __restrict__ deg) {
    int i = blockIdx.x * blockDim.x + threadIdx.x;
    if (i < E) atomicAdd(&deg[ei[E + i]], 1);
}
__global__ void dis_kernel(const int* __restrict__ deg, float* __restrict__ dis, int n) {
    int i = blockIdx.x * blockDim.x + threadIdx.x;
    if (i < n) dis[i] = rsqrtf((float)deg[i] + 1.0f);
}

// ---------------- CSR build: scan + fill ------------------------------------
__global__ void scan_local(const int* __restrict__ cnt, int n, int* __restrict__ out,
                           int* __restrict__ bsum) {
    __shared__ int s[256];
    int base = blockIdx.x * 1024;
    int t = threadIdx.x;
    int v[4], sum = 0;
#pragma unroll
    for (int j = 0; j < 4; j++) {
        int i = base + t * 4 + j;
        v[j] = (i < n) ? cnt[i] : 0;
        sum += v[j];
    }
    s[t] = sum;
    __syncthreads();
    for (int off = 1; off < 256; off <<= 1) {
        int x = (t >= off) ? s[t - off] : 0;
        __syncthreads();
        s[t] += x;
        __syncthreads();
    }
    if (t == 255) bsum[blockIdx.x] = s[255];
    int run = (t > 0) ? s[t - 1] : 0;
#pragma unroll
    for (int j = 0; j < 4; j++) {
        int i = base + t * 4 + j;
        if (i < n) out[i] = run;
        run += v[j];
    }
}
__global__ void scan_bsum(int* __restrict__ bsum, int nb) {
    __shared__ int s[512];
    int t = threadIdx.x;
    s[t] = (t < nb) ? bsum[t] : 0;
    __syncthreads();
    for (int off = 1; off < 512; off <<= 1) {
        int x = (t >= off) ? s[t - off] : 0;
        __syncthreads();
        s[t] += x;
        __syncthreads();
    }
    if (t < nb) bsum[t] = (t > 0) ? s[t - 1] : 0;
}
__global__ void scan_add(int* __restrict__ out, const int* __restrict__ bsum, int n,
                         int* __restrict__ cursor) {
    int i = blockIdx.x * blockDim.x + threadIdx.x;
    if (i < n) {
        int v = out[i] + bsum[i >> 10];
        out[i] = v;
        cursor[i] = v;
    }
}
__global__ void fill_csr(const int* __restrict__ ei, int E, int* __restrict__ cursor,
                         int* __restrict__ csr) {
    int i = blockIdx.x * blockDim.x + threadIdx.x;
    if (i < E) {
        int r = ei[i], c = ei[E + i];
        int slot = atomicAdd(&cursor[c], 1);
        csr[slot] = r;
    }
}

__global__ void seg_bounds(const int* __restrict__ seg, int n, int nseg, int* __restrict__ start) {
    int f = blockIdx.x * blockDim.x + threadIdx.x;
    if (f > nseg) return;
    int lo = 0, hi = n;
    while (lo < hi) {
        int mid = (lo + hi) >> 1;
        if (seg[mid] < f) lo = mid + 1; else hi = mid;
    }
    start[f] = lo;
}

// ---------------- GEMM: H = relu(X @ W + b) [* dis[row]] --------------------
// 128x128 block tile, 8x8 thread tile, fma.rn.f32x2 packed math.
template<int K, bool SCALE>
__global__ __launch_bounds__(256, 2) void gemmx_kernel(
    const float* __restrict__ X, const float* __restrict__ W,
    const float* __restrict__ bias, const float* __restrict__ dis,
    float* __restrict__ H, int N) {
    __shared__ float Xs[32 * 132];   // transposed: Xs[k][r], pitch 132
    __shared__ float Ws[32 * 128];   // Ws[k][c]
    const int row0 = blockIdx.x * 128;
    const int tx = threadIdx.x & 15;
    const int ty = threadIdx.x >> 4;
    const int c0 = tx * 8, r0 = ty * 8;

    unsigned long long acc2[8][4];
#pragma unroll
    for (int r = 0; r < 8; r++)
#pragma unroll
        for (int j = 0; j < 4; j++) acc2[r][j] = 0ULL;

    for (int kc = 0; kc < K; kc += 32) {
#pragma unroll
        for (int i = threadIdx.x; i < 128 * 32; i += 256) {
            int k = i & 31, r = i >> 5;
            Xs[k * 132 + r] = X[(size_t)(row0 + r) * K + kc + k];
        }
#pragma unroll
        for (int i = threadIdx.x; i < 32 * 128; i += 256) {
            int c = i & 127, k = i >> 7;
            Ws[k * 128 + c] = W[(size_t)(kc + k) * 128 + c];
        }
        __syncthreads();
#pragma unroll 4
        for (int k = 0; k < 32; k++) {
            float4 al = *(const float4*)&Xs[k * 132 + r0];
            float4 ah = *(const float4*)&Xs[k * 132 + r0 + 4];
            ulonglong2 wl = *(const ulonglong2*)&Ws[k * 128 + c0];
            ulonglong2 wh = *(const ulonglong2*)&Ws[k * 128 + c0 + 4];
            unsigned long long w2[4];
            w2[0] = wl.x; w2[1] = wl.y; w2[2] = wh.x; w2[3] = wh.y;
            float a[8];
            a[0] = al.x; a[1] = al.y; a[2] = al.z; a[3] = al.w;
            a[4] = ah.x; a[5] = ah.y; a[6] = ah.z; a[7] = ah.w;
#pragma unroll
            for (int r = 0; r < 8; r++) {
                unsigned long long a2;
                asm("mov.b64 %0, {%1, %1};" : "=l"(a2) : "f"(a[r]));
#pragma unroll
                for (int j = 0; j < 4; j++)
                    asm("fma.rn.f32x2 %0, %1, %2, %0;"
                        : "+l"(acc2[r][j]) : "l"(a2), "l"(w2[j]));
            }
        }
        __syncthreads();
    }

    float bb[8];
#pragma unroll
    for (int j = 0; j < 8; j++) bb[j] = bias[c0 + j];
#pragma unroll
    for (int r = 0; r < 8; r++) {
        int gr = row0 + r0 + r;
        if (gr >= N) return;
        float s = SCALE ? dis[gr] : 1.0f;
        float o[8];
#pragma unroll
        for (int j = 0; j < 4; j++) {
            float lo, hi;
            asm("mov.b64 {%0, %1}, %2;" : "=f"(lo), "=f"(hi) : "l"(acc2[r][j]));
            o[2 * j]     = fmaxf(lo + bb[2 * j], 0.f) * s;
            o[2 * j + 1] = fmaxf(hi + bb[2 * j + 1], 0.f) * s;
        }
        *(float4*)&H[(size_t)gr * 128 + c0]     = make_float4(o[0], o[1], o[2], o[3]);
        *(float4*)&H[(size_t)gr * 128 + c0 + 4] = make_float4(o[4], o[5], o[6], o[7]);
    }
}

// ---------------- gather 64ch, dis folded on the fly -------------------------
// out[v] = (x[v]*dis[v] + sum_u x[u]*dis[u]) * dis[v]
__global__ __launch_bounds__(256) void gather64_kernel(
    const int* __restrict__ rowptr, const int* __restrict__ deg,
    const int* __restrict__ csr, const float* __restrict__ x,
    const float* __restrict__ dis, float* __restrict__ out, int n) {
    int node = (blockIdx.x * 256 + threadIdx.x) >> 5;
    int lane = threadIdx.x & 31;
    if (node >= n) return;
    const float2* x2 = (const float2*)x;
    float dn = dis[node];
    float2 v = x2[(size_t)node * 32 + lane];
    float2 acc; acc.x = v.x * dn; acc.y = v.y * dn;
    int start = rowptr[node], d = deg[node];
    for (int e = 0; e < d; e++) {
        int u = csr[start + e];
        float du = dis[u];
        float2 w = x2[(size_t)u * 32 + lane];
        acc.x += w.x * du; acc.y += w.y * du;
    }
    acc.x *= dn; acc.y *= dn;
    ((float2*)out)[(size_t)node * 32 + lane] = acc;
}

// ---------------- gather 128ch ------------------------------------------------
// PRESCALED: input already has dis[row] folded; else multiply per-source.
template<bool PRESCALED>
__global__ __launch_bounds__(256) void gather128_kernel(
    const int* __restrict__ rowptr, const int* __restrict__ deg,
    const int* __restrict__ csr, const float* __restrict__ hs,
    const float* __restrict__ dis, float* __restrict__ out, int n) {
    int node = (blockIdx.x * 256 + threadIdx.x) >> 5;
    int lane = threadIdx.x & 31;
    if (node >= n) return;
    const float4* hs4 = (const float4*)hs;
    float dn = dis[node];
    float4 acc = hs4[(size_t)node * 32 + lane];
    if (!PRESCALED) { acc.x *= dn; acc.y *= dn; acc.z *= dn; acc.w *= dn; }
    int start = rowptr[node], d = deg[node];
    for (int e = 0; e < d; e++) {
        int u = csr[start + e];
        float4 v = hs4[(size_t)u * 32 + lane];
        float du = PRESCALED ? 1.0f : dis[u];
        acc.x += v.x * du; acc.y += v.y * du;
        acc.z += v.z * du; acc.w += v.w * du;
    }
    acc.x *= dn; acc.y *= dn; acc.z *= dn; acc.w *= dn;
    ((float4*)out)[(size_t)node * 32 + lane] = acc;
}

// ---------------- function-level mean pool (input already relu'd) ------------
__global__ __launch_bounds__(256) void poolseg_kernel(
    const float* __restrict__ x, const int* __restrict__ start,
    float* __restrict__ pool, int nseg) {
    int f = (blockIdx.x * 256 + threadIdx.x) >> 5;
    int lane = threadIdx.x & 31;
    if (f >= nseg) return;
    int s = start[f], e = start[f + 1];
    const float4* x4 = (const float4*)x;
    float4 acc = make_float4(0.f, 0.f, 0.f, 0.f);
    for (int i = s; i < e; i++) {
        float4 v = x4[(size_t)i * 32 + lane];
        acc.x += v.x; acc.y += v.y; acc.z += v.z; acc.w += v.w;
    }
    float inv = 1.0f / (float)max(e - s, 1);
    acc.x *= inv; acc.y *= inv; acc.z *= inv; acc.w *= inv;
    ((float4*)pool)[(size_t)f * 32 + lane] = acc;
}

__global__ void assemble_kernel(const float* __restrict__ pool, const float* __restrict__ emb,
                                const int* __restrict__ src, const int* __restrict__ isext,
                                float* __restrict__ fx) {
    int i = blockIdx.x * blockDim.x + threadIdx.x;
    if (i >= N_FCG * D_H) return;
    int row = i >> 7, j = i & 127;
    int s = src[row];
    float v;
    if (isext[row] == 1) {
        int k = min(max(s, 0), VOCAB - 1);
        v = emb[(size_t)k * D_H + j];
    } else {
        int k = min(max(s, 0), N_FUNC - 1);
        v = pool[(size_t)k * D_H + j];
    }
    fx[i] = v;
}

// binary-level mean pool (input already relu'd)
__global__ __launch_bounds__(128) void gpool_kernel(
    const float* __restrict__ y, const int* __restrict__ start, float* __restrict__ g) {
    int b = blockIdx.x, col = threadIdx.x;
    int s = start[b], e = start[b + 1];
    float acc = 0.f;
    for (int i = s; i < e; i++) acc += y[(size_t)i * 128 + col];
    g[b * 128 + col] = acc / (float)max(e - s, 1);
}

// MLP head + sigmoid
__global__ __launch_bounds__(256) void head_kernel(
    const float* __restrict__ g,
    const float* __restrict__ Wp1, const float* __restrict__ bp1,
    const float* __restrict__ Wp2, const float* __restrict__ bp2,
    const float* __restrict__ Wp3, const float* __restrict__ bp3,
    float* __restrict__ out) {
    __shared__ float G[NB * 128], H1[NB * 64], H2[NB * 32];
    int t = threadIdx.x;
    for (int i = t; i < NB * 128; i += 256) G[i] = g[i];
    __syncthreads();
    for (int i = t; i < NB * 64; i += 256) {
        int r = i >> 6, c = i & 63;
        float a = bp1[c];
        for (int k = 0; k < 128; k++) a += G[r * 128 + k] * Wp1[k * 64 + c];
        H1[i] = fmaxf(a, 0.f);
    }
    __syncthreads();
    for (int i = t; i < NB * 32; i += 256) {
        int r = i >> 5, c = i & 31;
        float a = bp2[c];
        for (int k = 0; k < 64; k++) a += H1[r * 64 + k] * Wp2[k * 32 + c];
        H2[i] = fmaxf(a, 0.f);
    }
    __syncthreads();
    if (t < NB) {
        float a = bp3[0];
        for (int k = 0; k < 32; k++) a += H2[t * 32 + k] * Wp3[k];
        out[t] = 1.0f / (1.0f + expf(-a));
    }
}

// ---------------- launch ----------------------------------------------------
extern "C" void kernel_launch(void* const* d_in, const int* in_sizes, int n_in,
                              void* d_out, int out_size) {
    const float* cfg_x  = (const float*)d_in[0];
    const int*   cfg_ei = (const int*)  d_in[1];
    const int*   n2f    = (const int*)  d_in[2];
    const int*   fcg_ei = (const int*)  d_in[3];
    const int*   fbatch = (const int*)  d_in[4];
    const int*   fsrc   = (const int*)  d_in[5];
    const int*   fext   = (const int*)  d_in[6];
    const float* W1  = (const float*)d_in[7];
    const float* b1  = (const float*)d_in[8];
    const float* W2  = (const float*)d_in[9];
    const float* b2  = (const float*)d_in[10];
    const float* emb = (const float*)d_in[11];
    const float* Wf  = (const float*)d_in[12];
    const float* bf  = (const float*)d_in[13];
    const float* Wp1 = (const float*)d_in[14];
    const float* bp1 = (const float*)d_in[15];
    const float* Wp2 = (const float*)d_in[16];
    const float* bp2 = (const float*)d_in[17];
    const float* Wp3 = (const float*)d_in[18];
    const float* bp3 = (const float*)d_in[19];
    float* out = (float*)d_out;

    void *p;
    cudaGetSymbolAddress(&p, g_a);       float* A      = (float*)p;
    cudaGetSymbolAddress(&p, g_b);       float* Bb     = (float*)p;
    cudaGetSymbolAddress(&p, g_deg);     int*   deg    = (int*)p;
    cudaGetSymbolAddress(&p, g_dis);     float* dis    = (float*)p;
    cudaGetSymbolAddress(&p, g_rowptr);  int*   rowptr = (int*)p;
    cudaGetSymbolAddress(&p, g_cursor);  int*   cursor = (int*)p;
    cudaGetSymbolAddress(&p, g_csr);     int*   csr    = (int*)p;
    cudaGetSymbolAddress(&p, g_fdeg);    int*   fdeg   = (int*)p;
    cudaGetSymbolAddress(&p, g_fdis);    float* fdis   = (float*)p;
    cudaGetSymbolAddress(&p, g_frowptr); int*   frowptr= (int*)p;
    cudaGetSymbolAddress(&p, g_fcursor); int*   fcursor= (int*)p;
    cudaGetSymbolAddress(&p, g_fcsr);    int*   fcsr   = (int*)p;
    cudaGetSymbolAddress(&p, g_bsum);    int*   bsum   = (int*)p;
    cudaGetSymbolAddress(&p, g_fstart);  int*   fstart = (int*)p;
    cudaGetSymbolAddress(&p, g_bstart);  int*   bstart = (int*)p;
    cudaGetSymbolAddress(&p, g_pool);    float* pool   = (float*)p;
    cudaGetSymbolAddress(&p, g_fx);      float* fx     = (float*)p;
    cudaGetSymbolAddress(&p, g_fz);      float* fz     = (float*)p;
    cudaGetSymbolAddress(&p, g_fy);      float* fy     = (float*)p;
    cudaGetSymbolAddress(&p, g_g);       float* gg     = (float*)p;

    // degrees + norms
    zerodeg_kernel<<<(N_CFG + 255) / 256, 256>>>();
    degi_kernel<<<(E_CFG + 255) / 256, 256>>>(cfg_ei, E_CFG, deg);
    degi_kernel<<<(E_FCG + 255) / 256, 256>>>(fcg_ei, E_FCG, fdeg);
    dis_kernel<<<(N_CFG + 255) / 256, 256>>>(deg, dis, N_CFG);
    dis_kernel<<<(N_FCG + 255) / 256, 256>>>(fdeg, fdis, N_FCG);

    // CSR build (CFG)
    const int NBLK_CFG = (N_CFG + 1023) / 1024;
    scan_local<<<NBLK_CFG, 256>>>(deg, N_CFG, rowptr, bsum);
    scan_bsum<<<1, 512>>>(bsum, NBLK_CFG);
    scan_add<<<(N_CFG + 255) / 256, 256>>>(rowptr, bsum, N_CFG, cursor);
    fill_csr<<<(E_CFG + 255) / 256, 256>>>(cfg_ei, E_CFG, cursor, csr);

    // CSR build (FCG)
    const int NBLK_FCG = (N_FCG + 1023) / 1024;
    scan_local<<<NBLK_FCG, 256>>>(fdeg, N_FCG, frowptr, bsum);
    scan_bsum<<<1, 512>>>(bsum, NBLK_FCG);
    scan_add<<<(N_FCG + 255) / 256, 256>>>(frowptr, bsum, N_FCG, fcursor);
    fill_csr<<<(E_FCG + 255) / 256, 256>>>(fcg_ei, E_FCG, fcursor, fcsr);

    // sorted-segment bounds
    seg_bounds<<<(N_FUNC + 256) / 256, 256>>>(n2f, N_CFG, N_FUNC, fstart);
    seg_bounds<<<1, 32>>>(fbatch, N_FCG, NB, bstart);

    // CFG layer 1: z1 = Ahat(cfg_x)  [64ch], then hs2 = relu(z1@W1+b1)*dis
    gather64_kernel<<<(N_CFG * 32 + 255) / 256, 256>>>(rowptr, deg, csr, cfg_x, dis, Bb, N_CFG);
    gemmx_kernel<64, true><<<N_CFG / 128, 256>>>(Bb, W1, b1, dis, A, N_CFG);

    // CFG layer 2: z2 = Ahat(hs2) (prescaled), then x2 = relu(z2@W2+b2)
    gather128_kernel<true><<<(N_CFG * 32 + 255) / 256, 256>>>(rowptr, deg, csr, A, dis, Bb, N_CFG);
    gemmx_kernel<128, false><<<N_CFG / 128, 256>>>(Bb, W2, b2, dis, A, N_CFG);

    // function-level mean pool
    poolseg_kernel<<<(N_FUNC * 32 + 255) / 256, 256>>>(A, fstart, pool, N_FUNC);

    // FCG features + FCG layer (dis folded on the fly in gather)
    assemble_kernel<<<(N_FCG * D_H) / 256, 256>>>(pool, emb, fsrc, fext, fx);
    gather128_kernel<false><<<(N_FCG * 32 + 255) / 256, 256>>>(frowptr, fdeg, fcsr, fx, fdis, fz, N_FCG);
    gemmx_kernel<128, false><<<N_FCG / 128, 256>>>(fz, Wf, bf, fdis, fy, N_FCG);

    // binary-level mean pool + head
    gpool_kernel<<<NB, 128>>>(fy, bstart, gg);
    head_kernel<<<1, 256>>>(gg, Wp1, bp1, Wp2, bp2, Wp3, bp3, out);
}